// round 16
// baseline (speedup 1.0000x reference)
#include <cuda_runtime.h>
#include <cstdint>
#include <cstddef>

// ---------------------------------------------------------------------------
// ParallelMoELinear: out[t,:] = tokens[t,:] @ W[e(t)] + bias[e(t)]
// E=8, T=4096, D_IN=1024, D_OUT=4096, 512 tokens/expert (sorted).
// sm_100 legacy tensor path (tcgen05 unavailable at this compile target).
//
// FINAL (champion R12/R15, 166-168us reproduced) + streaming epilogue stores:
//  - mma.sync.m16n8k8 tf32; HW truncation of A and W with the combined
//    deterministic bias cancelled by OUT_SCALE in the epilogue (3.12e-4).
//  - 256 threads, 2x4 warp grid, 64x32 warp tiles, 128x128x32 CTA tiles
//    (the only shape fitting 3 stages x 2 CTAs/SM in SMEM).
//  - 3-stage cp.async ring with per-stage full/empty mbarriers; warps drift
//    freely -- no CTA-wide barrier in the mainloop (R10's +24% win).
//  - period-3 unroll: all stage indices / mbarrier addresses / SMEM bases
//    compile-time constants; loop-carried state = 2 parity bits + 2 pointers.
//  - st.global.cs for output (written once, never read): evict-first keeps
//    L2 capacity for the 128MB W read stream. Pure hint, zero risk.
// Falsified: more warps (R3/R6), persistence (R7/R8), paired waits (R14),
// smaller bytes/MAC (R13). Residual ~25% tensor idle = laggard-warp resync
// at the empty-wait, structural to the synchronous-MMA pipeline.
// ---------------------------------------------------------------------------
static constexpr int D_IN  = 1024;
static constexpr int D_OUT = 4096;
static constexpr int T_TOK = 4096;

static constexpr int BM = 128;
static constexpr int BN = 128;
static constexpr int BK = 32;
static constexpr int NSTAGE = 3;
static constexpr int NKT = D_IN / BK;       // 32
static constexpr int NTHREADS = 256;        // 8 warps: 2 (M) x 4 (N), 64x32 tiles

static constexpr float OUT_SCALE = 1.000676f;   // (1+3.38e-4)^2: A+W truncation bias

// SMEM geometry (word = 4B):
//  A tile: [BM][AROW_W], AROW_W = 36 (32 data + 4 pad)
//    -> LDSM row stride 144B == 4 mod 32 words: conflict-free ldmatrix.
//  B tile: [BK][BROW_W], BROW_W = 136 (128 data + 8 pad)
//    -> scalar B-frag banks = 8*(lane%4) + lane/4: all 32 distinct.
static constexpr int AROW_W = 36;
static constexpr int BROW_W = 136;
static constexpr uint32_t A_STAGE_B = BM * AROW_W * 4;        // 18432
static constexpr uint32_t B_STAGE_B = BK * BROW_W * 4;        // 17408
static constexpr uint32_t SMEM_B0   = NSTAGE * A_STAGE_B;     // 55296
static constexpr uint32_t SMEM_MBAR = SMEM_B0 + NSTAGE * B_STAGE_B;  // 107520
// full[s] at MBAR + s*16, empty[s] at MBAR + s*16 + 8
static constexpr uint32_t SMEM_TOTAL = SMEM_MBAR + NSTAGE * 16;      // 107568

// ---------------------------------------------------------------------------
// PTX helpers (sm_80+)
// ---------------------------------------------------------------------------
__device__ __forceinline__ uint32_t smem_to_u32(const void* p) {
    uint32_t a;
    asm("{ .reg .u64 t; cvta.to.shared.u64 t, %1; cvt.u32.u64 %0, t; }"
        : "=r"(a) : "l"(p));
    return a;
}

#define CP_ASYNC_16(dst, src) \
    asm volatile("cp.async.cg.shared.global [%0], [%1], 16;" \
        :: "r"(dst), "l"(src) : "memory")

#define CP_ASYNC_MBAR_ARRIVE(mbar) \
    asm volatile("cp.async.mbarrier.arrive.noinc.shared.b64 [%0];" \
        :: "r"((uint32_t)(mbar)) : "memory")

#define MBARRIER_INIT(mbar, count) \
    asm volatile("mbarrier.init.shared.b64 [%0], %1;" \
        :: "r"((uint32_t)(mbar)), "r"((uint32_t)(count)) : "memory")

#define MBARRIER_ARRIVE(mbar) \
    asm volatile("mbarrier.arrive.shared.b64 _, [%0];" \
        :: "r"((uint32_t)(mbar)) : "memory")

#define MBARRIER_WAIT_PARITY(mbar_smem_addr, phase_parity) do { \
    uint32_t _mbar = (uint32_t)(mbar_smem_addr); \
    uint32_t _parity = (uint32_t)(phase_parity); \
    uint32_t _done; \
    asm volatile( \
        "{\n\t.reg .pred p;\n\t" \
        "mbarrier.try_wait.parity.acquire.cta.shared::cta.b64 p, [%1], %2;\n\t" \
        "selp.b32 %0, 1, 0, p;\n\t}" \
        : "=r"(_done) : "r"(_mbar), "r"(_parity) : "memory"); \
    if (!_done) { \
        asm volatile( \
            "{\n\t.reg .pred P1;\n\t" \
            "WAIT_LOOP_%=:\n\t" \
            "mbarrier.try_wait.parity.acquire.cta.shared::cta.b64 P1, [%0], %1, 0x989680;\n\t" \
            "@P1 bra.uni WAIT_DONE_%=;\n\t" \
            "bra.uni WAIT_LOOP_%=;\n\t" \
            "WAIT_DONE_%=:\n\t}" \
            :: "r"(_mbar), "r"(_parity) : "memory"); \
    } \
} while (0)

#define LDSM_X4(r, addr) \
    asm volatile("ldmatrix.sync.aligned.m8n8.x4.shared.b16 {%0,%1,%2,%3}, [%4];" \
        : "=r"((r)[0]), "=r"((r)[1]), "=r"((r)[2]), "=r"((r)[3]) \
        : "r"(addr))

#define LDS32(r, addr) \
    asm volatile("ld.shared.b32 %0, [%1];" : "=r"(r) : "r"(addr))

#define MMA_TF32(d, a, b) \
    asm volatile( \
        "mma.sync.aligned.m16n8k8.row.col.f32.tf32.tf32.f32 " \
        "{%0,%1,%2,%3}, {%4,%5,%6,%7}, {%8,%9}, {%0,%1,%2,%3};" \
        : "+f"((d)[0]), "+f"((d)[1]), "+f"((d)[2]), "+f"((d)[3]) \
        : "r"((a)[0]), "r"((a)[1]), "r"((a)[2]), "r"((a)[3]), \
          "r"((b)[0]), "r"((b)[1]))

// Streaming (evict-first) 8B store: output is write-once, never re-read.
#define STG_CS_64(addr, v) \
    asm volatile("st.global.cs.v2.f32 [%0], {%1, %2};" \
        :: "l"(addr), "f"((v).x), "f"((v).y) : "memory")

// ---------------------------------------------------------------------------
// GEMM kernel
// ---------------------------------------------------------------------------
__global__ void __launch_bounds__(NTHREADS, 2)
moe_tf32_mma_kernel(const float* __restrict__ tokens,
                    const float* __restrict__ W,
                    const float* __restrict__ bias,
                    const int* __restrict__ experts,
                    float* __restrict__ out) {
    extern __shared__ char smem[];
    const uint32_t sb = smem_to_u32(smem);

    const int tid  = threadIdx.x;
    const int lane = tid & 31;
    const int wid  = tid >> 5;
    const int warp_m = wid & 1;       // 2 warps in M -> 64-row warp tiles
    const int warp_n = wid >> 1;      // 4 warps in N -> 32-col warp tiles

    const int m_base = blockIdx.y * BM;
    const int n_base = blockIdx.x * BN;
    const int e = experts[m_base];    // uniform within 128-row tile (128 | 512)

    // ---- producer: per-thread cp.async addresses (advance by constants) ----
    static constexpr int A_GSTRIDE = 32 * D_IN;          // id += 256 -> +32 rows
    static constexpr uint32_t A_SSTRIDE = 32 * AROW_W * 4;
    static constexpr int B_GSTRIDE = 8 * D_OUT;          // id += 256 -> +8 k-rows
    static constexpr uint32_t B_SSTRIDE = 8 * BROW_W * 4;

    const float* ag = tokens + (size_t)m_base * D_IN +
                      (size_t)(tid >> 3) * D_IN + (tid & 7) * 4;        // chunk 0
    const float* bg = W + (size_t)e * D_IN * D_OUT + n_base +
                      (size_t)(tid >> 5) * D_OUT + (tid & 31) * 4;      // chunk 0
    const uint32_t as_p = sb + (uint32_t)((tid >> 3) * (AROW_W * 4) + (tid & 7) * 16);
    const uint32_t bs_p = sb + SMEM_B0 +
                          (uint32_t)((tid >> 5) * (BROW_W * 4) + (tid & 31) * 16);

    // ---- consumer: fragment base addresses ----
    const uint32_t ab = sb + (uint32_t)(warp_m * 64 * (AROW_W * 4)) +
                        (uint32_t)(((lane & 7) + ((lane >> 3) & 1) * 8) * (AROW_W * 4) +
                                   (lane >> 4) * 16);
    const uint32_t bb = sb + SMEM_B0 + (uint32_t)(warp_n * 32 * 4) +
                        (uint32_t)((lane & 3) * (BROW_W * 4) + (lane >> 2) * 4);

    // mbarriers: full[s] = mb + s*16 ; empty[s] = mb + s*16 + 8
    const uint32_t mb = sb + SMEM_MBAR;
    if (tid == 0) {
#pragma unroll
        for (int s = 0; s < NSTAGE; s++) {
            MBARRIER_INIT(mb + s * 16, NTHREADS);   // full: 256 cp.async arrivals
            MBARRIER_INIT(mb + s * 16 + 8, 8);      // empty: 1 per warp
        }
    }
    __syncthreads();   // init visibility (only CTA-wide barrier)

    float acc[4][4][4];
#pragma unroll
    for (int i = 0; i < 4; i++)
#pragma unroll
        for (int j = 0; j < 4; j++)
#pragma unroll
            for (int q = 0; q < 4; q++) acc[i][j][q] = 0.0f;

    // Issue the next chunk's loads into stage S (S compile-time constant);
    // ag/bg advance by one chunk afterwards.
    auto produce = [&](uint32_t a_ofs, uint32_t b_ofs) {
#pragma unroll
        for (int i = 0; i < 4; i++)
            CP_ASYNC_16(as_p + a_ofs + (uint32_t)i * A_SSTRIDE,
                        ag + (size_t)i * A_GSTRIDE);
#pragma unroll
        for (int i = 0; i < 4; i++)
            CP_ASYNC_16(bs_p + b_ofs + (uint32_t)i * B_SSTRIDE,
                        bg + (size_t)i * B_GSTRIDE);
        ag += BK;
        bg += (size_t)BK * D_OUT;
    };

    auto compute_chunk = [&](uint32_t a_ofs, uint32_t b_ofs) {
#pragma unroll
        for (int s = 0; s < BK / 8; s++) {          // 4 k-steps of 8
            uint32_t a[4][4];
#pragma unroll
            for (int im = 0; im < 4; im++)
                LDSM_X4(a[im], ab + a_ofs + (uint32_t)(im * 16 * (AROW_W * 4) + s * 32));
            uint32_t b[4][2];
#pragma unroll
            for (int jn = 0; jn < 4; jn++) {
                const uint32_t ba = bb + b_ofs + (uint32_t)(jn * 32 + s * 8 * (BROW_W * 4));
                LDS32(b[jn][0], ba);
                LDS32(b[jn][1], ba + 4 * (BROW_W * 4));
            }
#pragma unroll
            for (int im = 0; im < 4; im++)
#pragma unroll
                for (int jn = 0; jn < 4; jn++)
                    MMA_TF32(acc[im][jn], a[im], b[jn]);
        }
    };

    // ---- prologue: chunks 0,1 into stages 0,1 (fresh) ----
    produce(0, 0);                       CP_ASYNC_MBAR_ARRIVE(mb + 0 * 16);
    produce(A_STAGE_B, B_STAGE_B);       CP_ASYNC_MBAR_ARRIVE(mb + 1 * 16);

    // ---- peels: chunks 0,1,2 (consumer parities 0; producer fills 2,3,4) ----
    MBARRIER_WAIT_PARITY(mb + 0 * 16, 0);
    compute_chunk(0, 0);
    if (lane == 0) MBARRIER_ARRIVE(mb + 0 * 16 + 8);
    produce(2 * A_STAGE_B, 2 * B_STAGE_B);   CP_ASYNC_MBAR_ARRIVE(mb + 2 * 16);  // chunk 2 (fresh)

    MBARRIER_WAIT_PARITY(mb + 1 * 16, 0);
    compute_chunk(A_STAGE_B, B_STAGE_B);
    if (lane == 0) MBARRIER_ARRIVE(mb + 1 * 16 + 8);
    MBARRIER_WAIT_PARITY(mb + 0 * 16 + 8, 0);
    produce(0, 0);                           CP_ASYNC_MBAR_ARRIVE(mb + 0 * 16);  // chunk 3

    MBARRIER_WAIT_PARITY(mb + 2 * 16, 0);
    compute_chunk(2 * A_STAGE_B, 2 * B_STAGE_B);
    if (lane == 0) MBARRIER_ARRIVE(mb + 2 * 16 + 8);
    MBARRIER_WAIT_PARITY(mb + 1 * 16 + 8, 0);
    produce(A_STAGE_B, B_STAGE_B);           CP_ASYNC_MBAR_ARRIVE(mb + 1 * 16);  // chunk 4

    // ---- steady: 9 bodies, chunks 3..29, producing chunks 5..31 ----
    // Body j (1-based): consumer parity pc = j&1, stage-2 producer parity pp = pc^1.
    int pc = 1, pp = 0;
#pragma unroll 1
    for (int j = 0; j < 9; j++) {
        // chunk 3j+3 (stage 0); produce chunk 3j+5 -> stage 2
        MBARRIER_WAIT_PARITY(mb + 0 * 16, pc);
        compute_chunk(0, 0);
        if (lane == 0) MBARRIER_ARRIVE(mb + 0 * 16 + 8);
        MBARRIER_WAIT_PARITY(mb + 2 * 16 + 8, pp);
        produce(2 * A_STAGE_B, 2 * B_STAGE_B);   CP_ASYNC_MBAR_ARRIVE(mb + 2 * 16);

        // chunk 3j+4 (stage 1); produce chunk 3j+6 -> stage 0
        MBARRIER_WAIT_PARITY(mb + 1 * 16, pc);
        compute_chunk(A_STAGE_B, B_STAGE_B);
        if (lane == 0) MBARRIER_ARRIVE(mb + 1 * 16 + 8);
        MBARRIER_WAIT_PARITY(mb + 0 * 16 + 8, pc);
        produce(0, 0);                           CP_ASYNC_MBAR_ARRIVE(mb + 0 * 16);

        // chunk 3j+5 (stage 2); produce chunk 3j+7 -> stage 1
        MBARRIER_WAIT_PARITY(mb + 2 * 16, pc);
        compute_chunk(2 * A_STAGE_B, 2 * B_STAGE_B);
        if (lane == 0) MBARRIER_ARRIVE(mb + 2 * 16 + 8);
        MBARRIER_WAIT_PARITY(mb + 1 * 16 + 8, pc);
        produce(A_STAGE_B, B_STAGE_B);           CP_ASYNC_MBAR_ARRIVE(mb + 1 * 16);

        pc ^= 1; pp ^= 1;
    }

    // ---- tail: chunks 30 (stage 0), 31 (stage 1); parity = pc (= 0) ----
    MBARRIER_WAIT_PARITY(mb + 0 * 16, pc);
    compute_chunk(0, 0);
    MBARRIER_WAIT_PARITY(mb + 1 * 16, pc);
    compute_chunk(A_STAGE_B, B_STAGE_B);

    // ---- epilogue: bias-cancel scale + bias, streaming float2 stores ----
    const float* be = bias + (size_t)e * D_OUT + n_base + warp_n * 32;
    const int row0 = m_base + warp_m * 64 + (lane >> 2);
    const int col0 = n_base + warp_n * 32 + (lane & 3) * 2;

#pragma unroll
    for (int jn = 0; jn < 4; jn++) {
        const float2 bb2 = *reinterpret_cast<const float2*>(be + jn * 8 + (lane & 3) * 2);
#pragma unroll
        for (int im = 0; im < 4; im++) {
            const int r = row0 + im * 16;
            float2 v0 = make_float2(fmaf(acc[im][jn][0], OUT_SCALE, bb2.x),
                                    fmaf(acc[im][jn][1], OUT_SCALE, bb2.y));
            float2 v1 = make_float2(fmaf(acc[im][jn][2], OUT_SCALE, bb2.x),
                                    fmaf(acc[im][jn][3], OUT_SCALE, bb2.y));
            STG_CS_64(out + (size_t)r * D_OUT + col0 + jn * 8, v0);
            STG_CS_64(out + (size_t)(r + 8) * D_OUT + col0 + jn * 8, v1);
        }
    }
}

// ---------------------------------------------------------------------------
// Launch. Inputs (metadata order): sorted_tokens f32[4096,1024],
// kernel f32[8,1024,4096], bias f32[8,4096], group_sizes i32[8],
// sorted_experts i32[4096]. Output f32[4096,4096].
// ---------------------------------------------------------------------------
extern "C" void kernel_launch(void* const* d_in, const int* in_sizes, int n_in,
                              void* d_out, int out_size) {
    const float* tokens  = (const float*)d_in[0];
    const float* W       = (const float*)d_in[1];
    const float* bias    = (const float*)d_in[2];
    const int*   experts = (const int*)d_in[4];   // d_in[3] = group_sizes (unused)
    float* out = (float*)d_out;

    cudaFuncSetAttribute(moe_tf32_mma_kernel,
                         cudaFuncAttributeMaxDynamicSharedMemorySize, SMEM_TOTAL);
    dim3 grid(D_OUT / BN, T_TOK / BM);   // (32, 32)
    moe_tf32_mma_kernel<<<grid, NTHREADS, SMEM_TOTAL>>>(tokens, W, bias, experts, out);
}

// round 17
// speedup vs baseline: 1.0056x; 1.0056x over previous
#include <cuda_runtime.h>
#include <cstdint>
#include <cstddef>

// ---------------------------------------------------------------------------
// ParallelMoELinear: out[t,:] = tokens[t,:] @ W[e(t)] + bias[e(t)]
// E=8, T=4096, D_IN=1024, D_OUT=4096, 512 tokens/expert (sorted).
// sm_100 legacy tensor path (tcgen05 unavailable at this compile target).
//
// FINAL CHAMPION (R12/R15, 166-168us over three runs):
//  - mma.sync.m16n8k8 tf32; HW truncation of A and W with the combined
//    deterministic bias cancelled by OUT_SCALE in the epilogue (3.12e-4).
//  - 256 threads, 2x4 warp grid, 64x32 warp tiles, 128x128x32 CTA tiles
//    (the only shape fitting 3 stages x 2 CTAs/SM in SMEM).
//  - 3-stage cp.async ring with per-stage full/empty mbarriers
//    (cp.async.mbarrier.arrive tracks fills; per-warp arrives release);
//    warps drift freely -- no CTA-wide barrier in the mainloop (+24%).
//  - period-3 unroll: all stage indices / mbarrier addresses / SMEM bases
//    compile-time constants; loop-carried state = 2 parity bits + 2 pointers.
//  - 2 CTAs/SM; RF (128 regs x 512 thr) and SMEM (2 x 107.5KB) exactly full.
// Falsified: more warps (R3/R6), persistence (R7/R8), paired waits (R14),
// smaller bytes/MAC (R13), streaming stores (R16). Residual ~25% tensor idle
// = laggard-warp resync + LDSM ramp, structural to synchronous-MMA pipelines.
// ---------------------------------------------------------------------------
static constexpr int D_IN  = 1024;
static constexpr int D_OUT = 4096;
static constexpr int T_TOK = 4096;

static constexpr int BM = 128;
static constexpr int BN = 128;
static constexpr int BK = 32;
static constexpr int NSTAGE = 3;
static constexpr int NKT = D_IN / BK;       // 32
static constexpr int NTHREADS = 256;        // 8 warps: 2 (M) x 4 (N), 64x32 tiles

static constexpr float OUT_SCALE = 1.000676f;   // (1+3.38e-4)^2: A+W truncation bias

// SMEM geometry (word = 4B):
//  A tile: [BM][AROW_W], AROW_W = 36 (32 data + 4 pad)
//    -> LDSM row stride 144B == 4 mod 32 words: conflict-free ldmatrix.
//  B tile: [BK][BROW_W], BROW_W = 136 (128 data + 8 pad)
//    -> scalar B-frag banks = 8*(lane%4) + lane/4: all 32 distinct.
static constexpr int AROW_W = 36;
static constexpr int BROW_W = 136;
static constexpr uint32_t A_STAGE_B = BM * AROW_W * 4;        // 18432
static constexpr uint32_t B_STAGE_B = BK * BROW_W * 4;        // 17408
static constexpr uint32_t SMEM_B0   = NSTAGE * A_STAGE_B;     // 55296
static constexpr uint32_t SMEM_MBAR = SMEM_B0 + NSTAGE * B_STAGE_B;  // 107520
// full[s] at MBAR + s*16, empty[s] at MBAR + s*16 + 8
static constexpr uint32_t SMEM_TOTAL = SMEM_MBAR + NSTAGE * 16;      // 107568

// ---------------------------------------------------------------------------
// PTX helpers (sm_80+)
// ---------------------------------------------------------------------------
__device__ __forceinline__ uint32_t smem_to_u32(const void* p) {
    uint32_t a;
    asm("{ .reg .u64 t; cvta.to.shared.u64 t, %1; cvt.u32.u64 %0, t; }"
        : "=r"(a) : "l"(p));
    return a;
}

#define CP_ASYNC_16(dst, src) \
    asm volatile("cp.async.cg.shared.global [%0], [%1], 16;" \
        :: "r"(dst), "l"(src) : "memory")

#define CP_ASYNC_MBAR_ARRIVE(mbar) \
    asm volatile("cp.async.mbarrier.arrive.noinc.shared.b64 [%0];" \
        :: "r"((uint32_t)(mbar)) : "memory")

#define MBARRIER_INIT(mbar, count) \
    asm volatile("mbarrier.init.shared.b64 [%0], %1;" \
        :: "r"((uint32_t)(mbar)), "r"((uint32_t)(count)) : "memory")

#define MBARRIER_ARRIVE(mbar) \
    asm volatile("mbarrier.arrive.shared.b64 _, [%0];" \
        :: "r"((uint32_t)(mbar)) : "memory")

#define MBARRIER_WAIT_PARITY(mbar_smem_addr, phase_parity) do { \
    uint32_t _mbar = (uint32_t)(mbar_smem_addr); \
    uint32_t _parity = (uint32_t)(phase_parity); \
    uint32_t _done; \
    asm volatile( \
        "{\n\t.reg .pred p;\n\t" \
        "mbarrier.try_wait.parity.acquire.cta.shared::cta.b64 p, [%1], %2;\n\t" \
        "selp.b32 %0, 1, 0, p;\n\t}" \
        : "=r"(_done) : "r"(_mbar), "r"(_parity) : "memory"); \
    if (!_done) { \
        asm volatile( \
            "{\n\t.reg .pred P1;\n\t" \
            "WAIT_LOOP_%=:\n\t" \
            "mbarrier.try_wait.parity.acquire.cta.shared::cta.b64 P1, [%0], %1, 0x989680;\n\t" \
            "@P1 bra.uni WAIT_DONE_%=;\n\t" \
            "bra.uni WAIT_LOOP_%=;\n\t" \
            "WAIT_DONE_%=:\n\t}" \
            :: "r"(_mbar), "r"(_parity) : "memory"); \
    } \
} while (0)

#define LDSM_X4(r, addr) \
    asm volatile("ldmatrix.sync.aligned.m8n8.x4.shared.b16 {%0,%1,%2,%3}, [%4];" \
        : "=r"((r)[0]), "=r"((r)[1]), "=r"((r)[2]), "=r"((r)[3]) \
        : "r"(addr))

#define LDS32(r, addr) \
    asm volatile("ld.shared.b32 %0, [%1];" : "=r"(r) : "r"(addr))

#define MMA_TF32(d, a, b) \
    asm volatile( \
        "mma.sync.aligned.m16n8k8.row.col.f32.tf32.tf32.f32 " \
        "{%0,%1,%2,%3}, {%4,%5,%6,%7}, {%8,%9}, {%0,%1,%2,%3};" \
        : "+f"((d)[0]), "+f"((d)[1]), "+f"((d)[2]), "+f"((d)[3]) \
        : "r"((a)[0]), "r"((a)[1]), "r"((a)[2]), "r"((a)[3]), \
          "r"((b)[0]), "r"((b)[1]))

// ---------------------------------------------------------------------------
// GEMM kernel
// ---------------------------------------------------------------------------
__global__ void __launch_bounds__(NTHREADS, 2)
moe_tf32_mma_kernel(const float* __restrict__ tokens,
                    const float* __restrict__ W,
                    const float* __restrict__ bias,
                    const int* __restrict__ experts,
                    float* __restrict__ out) {
    extern __shared__ char smem[];
    const uint32_t sb = smem_to_u32(smem);

    const int tid  = threadIdx.x;
    const int lane = tid & 31;
    const int wid  = tid >> 5;
    const int warp_m = wid & 1;       // 2 warps in M -> 64-row warp tiles
    const int warp_n = wid >> 1;      // 4 warps in N -> 32-col warp tiles

    const int m_base = blockIdx.y * BM;
    const int n_base = blockIdx.x * BN;
    const int e = experts[m_base];    // uniform within 128-row tile (128 | 512)

    // ---- producer: per-thread cp.async addresses (advance by constants) ----
    static constexpr int A_GSTRIDE = 32 * D_IN;          // id += 256 -> +32 rows
    static constexpr uint32_t A_SSTRIDE = 32 * AROW_W * 4;
    static constexpr int B_GSTRIDE = 8 * D_OUT;          // id += 256 -> +8 k-rows
    static constexpr uint32_t B_SSTRIDE = 8 * BROW_W * 4;

    const float* ag = tokens + (size_t)m_base * D_IN +
                      (size_t)(tid >> 3) * D_IN + (tid & 7) * 4;        // chunk 0
    const float* bg = W + (size_t)e * D_IN * D_OUT + n_base +
                      (size_t)(tid >> 5) * D_OUT + (tid & 31) * 4;      // chunk 0
    const uint32_t as_p = sb + (uint32_t)((tid >> 3) * (AROW_W * 4) + (tid & 7) * 16);
    const uint32_t bs_p = sb + SMEM_B0 +
                          (uint32_t)((tid >> 5) * (BROW_W * 4) + (tid & 31) * 16);

    // ---- consumer: fragment base addresses ----
    const uint32_t ab = sb + (uint32_t)(warp_m * 64 * (AROW_W * 4)) +
                        (uint32_t)(((lane & 7) + ((lane >> 3) & 1) * 8) * (AROW_W * 4) +
                                   (lane >> 4) * 16);
    const uint32_t bb = sb + SMEM_B0 + (uint32_t)(warp_n * 32 * 4) +
                        (uint32_t)((lane & 3) * (BROW_W * 4) + (lane >> 2) * 4);

    // mbarriers: full[s] = mb + s*16 ; empty[s] = mb + s*16 + 8
    const uint32_t mb = sb + SMEM_MBAR;
    if (tid == 0) {
#pragma unroll
        for (int s = 0; s < NSTAGE; s++) {
            MBARRIER_INIT(mb + s * 16, NTHREADS);   // full: 256 cp.async arrivals
            MBARRIER_INIT(mb + s * 16 + 8, 8);      // empty: 1 per warp
        }
    }
    __syncthreads();   // init visibility (only CTA-wide barrier)

    float acc[4][4][4];
#pragma unroll
    for (int i = 0; i < 4; i++)
#pragma unroll
        for (int j = 0; j < 4; j++)
#pragma unroll
            for (int q = 0; q < 4; q++) acc[i][j][q] = 0.0f;

    // Issue the next chunk's loads into stage S (S compile-time constant);
    // ag/bg advance by one chunk afterwards.
    auto produce = [&](uint32_t a_ofs, uint32_t b_ofs) {
#pragma unroll
        for (int i = 0; i < 4; i++)
            CP_ASYNC_16(as_p + a_ofs + (uint32_t)i * A_SSTRIDE,
                        ag + (size_t)i * A_GSTRIDE);
#pragma unroll
        for (int i = 0; i < 4; i++)
            CP_ASYNC_16(bs_p + b_ofs + (uint32_t)i * B_SSTRIDE,
                        bg + (size_t)i * B_GSTRIDE);
        ag += BK;
        bg += (size_t)BK * D_OUT;
    };

    auto compute_chunk = [&](uint32_t a_ofs, uint32_t b_ofs) {
#pragma unroll
        for (int s = 0; s < BK / 8; s++) {          // 4 k-steps of 8
            uint32_t a[4][4];
#pragma unroll
            for (int im = 0; im < 4; im++)
                LDSM_X4(a[im], ab + a_ofs + (uint32_t)(im * 16 * (AROW_W * 4) + s * 32));
            uint32_t b[4][2];
#pragma unroll
            for (int jn = 0; jn < 4; jn++) {
                const uint32_t ba = bb + b_ofs + (uint32_t)(jn * 32 + s * 8 * (BROW_W * 4));
                LDS32(b[jn][0], ba);
                LDS32(b[jn][1], ba + 4 * (BROW_W * 4));
            }
#pragma unroll
            for (int im = 0; im < 4; im++)
#pragma unroll
                for (int jn = 0; jn < 4; jn++)
                    MMA_TF32(acc[im][jn], a[im], b[jn]);
        }
    };

    // ---- prologue: chunks 0,1 into stages 0,1 (fresh) ----
    produce(0, 0);                       CP_ASYNC_MBAR_ARRIVE(mb + 0 * 16);
    produce(A_STAGE_B, B_STAGE_B);       CP_ASYNC_MBAR_ARRIVE(mb + 1 * 16);

    // ---- peels: chunks 0,1,2 (consumer parities 0; producer fills 2,3,4) ----
    MBARRIER_WAIT_PARITY(mb + 0 * 16, 0);
    compute_chunk(0, 0);
    if (lane == 0) MBARRIER_ARRIVE(mb + 0 * 16 + 8);
    produce(2 * A_STAGE_B, 2 * B_STAGE_B);   CP_ASYNC_MBAR_ARRIVE(mb + 2 * 16);  // chunk 2 (fresh)

    MBARRIER_WAIT_PARITY(mb + 1 * 16, 0);
    compute_chunk(A_STAGE_B, B_STAGE_B);
    if (lane == 0) MBARRIER_ARRIVE(mb + 1 * 16 + 8);
    MBARRIER_WAIT_PARITY(mb + 0 * 16 + 8, 0);
    produce(0, 0);                           CP_ASYNC_MBAR_ARRIVE(mb + 0 * 16);  // chunk 3

    MBARRIER_WAIT_PARITY(mb + 2 * 16, 0);
    compute_chunk(2 * A_STAGE_B, 2 * B_STAGE_B);
    if (lane == 0) MBARRIER_ARRIVE(mb + 2 * 16 + 8);
    MBARRIER_WAIT_PARITY(mb + 1 * 16 + 8, 0);
    produce(A_STAGE_B, B_STAGE_B);           CP_ASYNC_MBAR_ARRIVE(mb + 1 * 16);  // chunk 4

    // ---- steady: 9 bodies, chunks 3..29, producing chunks 5..31 ----
    // Body j (1-based): consumer parity pc = j&1, stage-2 producer parity pp = pc^1.
    int pc = 1, pp = 0;
#pragma unroll 1
    for (int j = 0; j < 9; j++) {
        // chunk 3j+3 (stage 0); produce chunk 3j+5 -> stage 2
        MBARRIER_WAIT_PARITY(mb + 0 * 16, pc);
        compute_chunk(0, 0);
        if (lane == 0) MBARRIER_ARRIVE(mb + 0 * 16 + 8);
        MBARRIER_WAIT_PARITY(mb + 2 * 16 + 8, pp);
        produce(2 * A_STAGE_B, 2 * B_STAGE_B);   CP_ASYNC_MBAR_ARRIVE(mb + 2 * 16);

        // chunk 3j+4 (stage 1); produce chunk 3j+6 -> stage 0
        MBARRIER_WAIT_PARITY(mb + 1 * 16, pc);
        compute_chunk(A_STAGE_B, B_STAGE_B);
        if (lane == 0) MBARRIER_ARRIVE(mb + 1 * 16 + 8);
        MBARRIER_WAIT_PARITY(mb + 0 * 16 + 8, pc);
        produce(0, 0);                           CP_ASYNC_MBAR_ARRIVE(mb + 0 * 16);

        // chunk 3j+5 (stage 2); produce chunk 3j+7 -> stage 1
        MBARRIER_WAIT_PARITY(mb + 2 * 16, pc);
        compute_chunk(2 * A_STAGE_B, 2 * B_STAGE_B);
        if (lane == 0) MBARRIER_ARRIVE(mb + 2 * 16 + 8);
        MBARRIER_WAIT_PARITY(mb + 1 * 16 + 8, pc);
        produce(A_STAGE_B, B_STAGE_B);           CP_ASYNC_MBAR_ARRIVE(mb + 1 * 16);

        pc ^= 1; pp ^= 1;
    }

    // ---- tail: chunks 30 (stage 0), 31 (stage 1); parity = pc (= 0) ----
    MBARRIER_WAIT_PARITY(mb + 0 * 16, pc);
    compute_chunk(0, 0);
    MBARRIER_WAIT_PARITY(mb + 1 * 16, pc);
    compute_chunk(A_STAGE_B, B_STAGE_B);

    // ---- epilogue: bias-cancel scale + bias, store float2 pairs ----
    const float* be = bias + (size_t)e * D_OUT + n_base + warp_n * 32;
    const int row0 = m_base + warp_m * 64 + (lane >> 2);
    const int col0 = n_base + warp_n * 32 + (lane & 3) * 2;

#pragma unroll
    for (int jn = 0; jn < 4; jn++) {
        const float2 bb2 = *reinterpret_cast<const float2*>(be + jn * 8 + (lane & 3) * 2);
#pragma unroll
        for (int im = 0; im < 4; im++) {
            const int r = row0 + im * 16;
            float2 v0 = make_float2(fmaf(acc[im][jn][0], OUT_SCALE, bb2.x),
                                    fmaf(acc[im][jn][1], OUT_SCALE, bb2.y));
            float2 v1 = make_float2(fmaf(acc[im][jn][2], OUT_SCALE, bb2.x),
                                    fmaf(acc[im][jn][3], OUT_SCALE, bb2.y));
            *reinterpret_cast<float2*>(out + (size_t)r * D_OUT + col0 + jn * 8) = v0;
            *reinterpret_cast<float2*>(out + (size_t)(r + 8) * D_OUT + col0 + jn * 8) = v1;
        }
    }
}

// ---------------------------------------------------------------------------
// Launch. Inputs (metadata order): sorted_tokens f32[4096,1024],
// kernel f32[8,1024,4096], bias f32[8,4096], group_sizes i32[8],
// sorted_experts i32[4096]. Output f32[4096,4096].
// ---------------------------------------------------------------------------
extern "C" void kernel_launch(void* const* d_in, const int* in_sizes, int n_in,
                              void* d_out, int out_size) {
    const float* tokens  = (const float*)d_in[0];
    const float* W       = (const float*)d_in[1];
    const float* bias    = (const float*)d_in[2];
    const int*   experts = (const int*)d_in[4];   // d_in[3] = group_sizes (unused)
    float* out = (float*)d_out;

    cudaFuncSetAttribute(moe_tf32_mma_kernel,
                         cudaFuncAttributeMaxDynamicSharedMemorySize, SMEM_TOTAL);
    dim3 grid(D_OUT / BN, T_TOK / BM);   // (32, 32)
    moe_tf32_mma_kernel<<<grid, NTHREADS, SMEM_TOTAL>>>(tokens, W, bias, experts, out);
}